// round 1
// baseline (speedup 1.0000x reference)
#include <cuda_runtime.h>
#include <cstddef>

// ---------------------------------------------------------------------------
// Problem constants (fixed by setup_inputs)
// ---------------------------------------------------------------------------
#define BATCH   4096
#define TT      2
#define NTOK    49
#define CDIM    192
#define NHEAD   6
#define HDIM    32
#define KDIM    192

#define M_Q   (BATCH * NTOK)          // 200704
#define M_KV  (BATCH * TT * NTOK)     // 401408

// Scratch (device globals: allocation-free rule)
__device__ float g_q [(size_t)M_Q  * CDIM];        // 154 MB  (B*N, 192)
__device__ float g_kv[(size_t)M_KV * 2 * CDIM];    // 616 MB  (B*T*N, 384)
__device__ float g_ao[(size_t)M_KV * CDIM];        // 308 MB  (B*T*N, 192)

// ---------------------------------------------------------------------------
// GEMM: out[m][c] = sum_k A[m][k] * W[c][k] + bias[c]
// A: [M x 192] row-major.  W: [NC x 192] row-major.  M % 64 == 0, NC % 64 == 0.
// Tile 64x64x32, 256 threads, 4x4 micro-tile.
// ---------------------------------------------------------------------------
#define BM 64
#define BN 64
#define BK 32
#define APAD 68   // 68*4 bytes = 272 = 16-byte aligned rows, (4k+m)%32 banks

__global__ __launch_bounds__(256) void gemm_bias(
    const float* __restrict__ A, const float* __restrict__ W,
    const float* __restrict__ bias, float* __restrict__ out, int NC)
{
    __shared__ __align__(16) float As[BK][APAD];
    __shared__ __align__(16) float Ws[BK][APAD];

    const int tid = threadIdx.x;
    const int ty  = tid >> 4;      // 0..15 (A rows)
    const int tx  = tid & 15;      // 0..15 (W rows / out cols)

    const float* Ablk = A + (size_t)blockIdx.y * BM * KDIM;
    const float* Wblk = W + (size_t)blockIdx.x * BN * KDIM;

    float acc[4][4] = {};

    for (int k0 = 0; k0 < KDIM; k0 += BK) {
#pragma unroll
        for (int r = 0; r < 2; r++) {
            int idx = tid + r * 256;           // 0..511
            int row = idx >> 3;                // 0..63
            int k4  = (idx & 7) << 2;          // 0,4,...,28
            float4 a = *(const float4*)&Ablk[row * KDIM + k0 + k4];
            As[k4 + 0][row] = a.x; As[k4 + 1][row] = a.y;
            As[k4 + 2][row] = a.z; As[k4 + 3][row] = a.w;
            float4 w = *(const float4*)&Wblk[row * KDIM + k0 + k4];
            Ws[k4 + 0][row] = w.x; Ws[k4 + 1][row] = w.y;
            Ws[k4 + 2][row] = w.z; Ws[k4 + 3][row] = w.w;
        }
        __syncthreads();

#pragma unroll
        for (int kk = 0; kk < BK; kk++) {
            float4 a = *(const float4*)&As[kk][ty << 2];
            float4 b = *(const float4*)&Ws[kk][tx << 2];
            float av[4] = {a.x, a.y, a.z, a.w};
            float bv[4] = {b.x, b.y, b.z, b.w};
#pragma unroll
            for (int i = 0; i < 4; i++)
#pragma unroll
                for (int j = 0; j < 4; j++)
                    acc[i][j] += av[i] * bv[j];
        }
        __syncthreads();
    }

    const int orow = blockIdx.y * BM + (ty << 2);
    const int ocol = blockIdx.x * BN + (tx << 2);
    float4 bb = *(const float4*)&bias[ocol];
    float bv[4] = {bb.x, bb.y, bb.z, bb.w};
#pragma unroll
    for (int i = 0; i < 4; i++) {
        float4 r;
        r.x = acc[i][0] + bv[0];
        r.y = acc[i][1] + bv[1];
        r.z = acc[i][2] + bv[2];
        r.w = acc[i][3] + bv[3];
        *(float4*)&out[(size_t)(orow + i) * NC + ocol] = r;
    }
}

// ---------------------------------------------------------------------------
// Fused attention: one block per (b, t, h).
//   S = (Q K^T) * scale + bias(h, n, m); softmax rows; O = P V
// Q: [B*N, 192] (head slice h*32).  KV: [B*T*N, 384] (k at h*32, v at 192+h*32).
// O: [B*T*N, 192], written at column h*32 (ready for proj GEMM).
// ---------------------------------------------------------------------------
__global__ __launch_bounds__(128) void attn_kernel(
    const float* __restrict__ Q, const float* __restrict__ KV,
    const float* __restrict__ rpb, float* __restrict__ O)
{
    const int blk = blockIdx.x;          // B*T*H blocks
    const int h   = blk % NHEAD;
    const int bt  = blk / NHEAD;         // 0..8191  (= b*T + t)
    const int b   = bt / TT;

    __shared__ float qs[NTOK][HDIM];       // 32 stride (broadcast reads)
    __shared__ float ks[NTOK][HDIM + 1];   // pad 33: conflict-free m-major reads
    __shared__ float vs[NTOK][HDIM + 1];
    __shared__ float S [NTOK][53];         // pad 53: conflict-free row scans

    const int tid = threadIdx.x;  // 128

    // Load q, k, v head slices (float4 global reads, scalar smem stores)
    for (int i = tid; i < NTOK * 8; i += 128) {
        int n  = i >> 3;
        int c4 = (i & 7) << 2;
        float4 q = *(const float4*)&Q[((size_t)(b * NTOK + n)) * CDIM + h * HDIM + c4];
        qs[n][c4 + 0] = q.x; qs[n][c4 + 1] = q.y; qs[n][c4 + 2] = q.z; qs[n][c4 + 3] = q.w;
        size_t kvbase = (size_t)(bt * NTOK + n) * (2 * CDIM) + h * HDIM + c4;
        float4 k = *(const float4*)&KV[kvbase];
        ks[n][c4 + 0] = k.x; ks[n][c4 + 1] = k.y; ks[n][c4 + 2] = k.z; ks[n][c4 + 3] = k.w;
        float4 v = *(const float4*)&KV[kvbase + CDIM];
        vs[n][c4 + 0] = v.x; vs[n][c4 + 1] = v.y; vs[n][c4 + 2] = v.z; vs[n][c4 + 3] = v.w;
    }
    __syncthreads();

    const float scale = 0.17677669529663687f;   // 32^-0.5

    // S = QK^T * scale + relative position bias
    for (int idx = tid; idx < NTOK * NTOK; idx += 128) {
        int n = idx / NTOK, m = idx % NTOK;
        float acc = 0.f;
#pragma unroll
        for (int k = 0; k < HDIM; k++) acc += qs[n][k] * ks[m][k];
        int nh = n / 7, nw = n % 7, mh = m / 7, mw = m % 7;
        int ridx = (nh - mh + 6) * 13 + (nw - mw + 6);
        S[n][m] = acc * scale + rpb[ridx * NHEAD + h];
    }
    __syncthreads();

    // Row softmax (one thread per row)
    if (tid < NTOK) {
        int n = tid;
        float mx = -1e30f;
#pragma unroll
        for (int m = 0; m < NTOK; m++) mx = fmaxf(mx, S[n][m]);
        float sum = 0.f;
#pragma unroll
        for (int m = 0; m < NTOK; m++) { float e = __expf(S[n][m] - mx); S[n][m] = e; sum += e; }
        float inv = 1.f / sum;
#pragma unroll
        for (int m = 0; m < NTOK; m++) S[n][m] *= inv;
    }
    __syncthreads();

    // O = P V, write head slice into (B*T*N, 192) layout
    for (int idx = tid; idx < NTOK * HDIM; idx += 128) {
        int n = idx >> 5, dd = idx & 31;
        float acc = 0.f;
#pragma unroll
        for (int m = 0; m < NTOK; m++) acc += S[n][m] * vs[m][dd];
        O[(size_t)(bt * NTOK + n) * CDIM + h * HDIM + dd] = acc;
    }
}

// ---------------------------------------------------------------------------
// kernel_launch
// inputs: x, memory, w_q, b_q, w_kv, b_kv, w_proj, b_proj, rpb_table
// ---------------------------------------------------------------------------
extern "C" void kernel_launch(void* const* d_in, const int* in_sizes, int n_in,
                              void* d_out, int out_size)
{
    const float* x      = (const float*)d_in[0];
    const float* memory = (const float*)d_in[1];
    const float* w_q    = (const float*)d_in[2];
    const float* b_q    = (const float*)d_in[3];
    const float* w_kv   = (const float*)d_in[4];
    const float* b_kv   = (const float*)d_in[5];
    const float* w_proj = (const float*)d_in[6];
    const float* b_proj = (const float*)d_in[7];
    const float* rpb    = (const float*)d_in[8];
    float* out = (float*)d_out;

    float *gq, *gkv, *gao;
    cudaGetSymbolAddress((void**)&gq,  g_q);
    cudaGetSymbolAddress((void**)&gkv, g_kv);
    cudaGetSymbolAddress((void**)&gao, g_ao);

    // Q projection: [200704 x 192] @ [192 x 192]^T
    gemm_bias<<<dim3(CDIM / BN, M_Q / BM), 256>>>(x, w_q, b_q, gq, CDIM);
    // KV projection: [401408 x 192] @ [384 x 192]^T
    gemm_bias<<<dim3(2 * CDIM / BN, M_KV / BM), 256>>>(memory, w_kv, b_kv, gkv, 2 * CDIM);
    // Fused attention per (b, t, h)
    attn_kernel<<<BATCH * TT * NHEAD, 128>>>(gq, gkv, rpb, gao);
    // Output projection: [401408 x 192] @ [192 x 192]^T -> d_out
    gemm_bias<<<dim3(CDIM / BN, M_KV / BM), 256>>>(gao, w_proj, b_proj, out, CDIM);
}

// round 6
// speedup vs baseline: 1.8620x; 1.8620x over previous
#include <cuda_runtime.h>
#include <cstdint>
#include <cstddef>

// ---------------------------------------------------------------------------
// Problem constants
// ---------------------------------------------------------------------------
#define BATCH   4096
#define TT      2
#define NTOK    49
#define CDIM    192
#define NHEAD   6
#define HDIM    32

#define M_Q   (BATCH * NTOK)          // 200704
#define M_KV  (BATCH * TT * NTOK)     // 401408

// Scratch (device globals: allocation-free rule)
__device__ float g_q [(size_t)M_Q  * CDIM];
__device__ float g_kv[(size_t)M_KV * 2 * CDIM];
__device__ float g_ao[(size_t)M_KV * CDIM];

// ---------------------------------------------------------------------------
// Helpers
// ---------------------------------------------------------------------------
__device__ __forceinline__ uint32_t f2tf32(float f) {   // round-to-nearest tf32
    uint32_t u;
    asm("cvt.rna.tf32.f32 %0, %1;" : "=r"(u) : "f"(f));
    return u;
}
__device__ __forceinline__ void mma_tf32(float* d, const uint32_t* a,
                                         uint32_t b0, uint32_t b1) {
    asm volatile(
        "mma.sync.aligned.m16n8k8.row.col.f32.tf32.tf32.f32 "
        "{%0,%1,%2,%3}, {%4,%5,%6,%7}, {%8,%9}, {%0,%1,%2,%3};"
        : "+f"(d[0]), "+f"(d[1]), "+f"(d[2]), "+f"(d[3])
        : "r"(a[0]), "r"(a[1]), "r"(a[2]), "r"(a[3]), "r"(b0), "r"(b1));
}

// ---------------------------------------------------------------------------
// Tensor-core GEMM via mma.sync tf32 (arch-agnostic PTX; no tcgen05)
// out[m][c] = sum_k A[m][k] * W[c][k] + bias[c]
// CTA tile: 128 x 192.  gridDim.y = NCTOT/192 column blocks.
// 8 warps, warp tile 32x96 (2 x 12 m16n8k8 fragments).
// K chunks of 32, 2-stage smem double buffer, register-prefetched LDG.
// smem rows padded to 36 floats: fragment LDS bank = (4*row + k) % 32,
// conflict-free for both A (rows=gid span 8) and B (rows=gid span 8).
// ---------------------------------------------------------------------------
#define GBK   32
#define APADW 36
#define ASZ   (128 * APADW)           // floats per A stage
#define BSZ   (192 * APADW)           // floats per W stage

template<int NCTOT>
__global__ __launch_bounds__(256, 1)
void gemm_mma(const float* __restrict__ A, const float* __restrict__ W,
              const float* __restrict__ bias, float* __restrict__ out)
{
    extern __shared__ float sm[];
    const int tid  = threadIdx.x;
    const int wid  = tid >> 5;
    const int lane = tid & 31;
    const int wm   = wid & 3;          // warp row   (4 x 32)
    const int wn   = wid >> 2;         // warp col   (2 x 96)
    const int gid  = lane >> 2;        // 0..7
    const int tc   = lane & 3;         // 0..3

    const size_t mbase = (size_t)blockIdx.x * 128;
    const int    nbase = blockIdx.y * 192;
    const float* Ablk = A + mbase * CDIM;
    const float* Wblk = W + (size_t)nbase * CDIM;

    float acc[2][12][4];
#pragma unroll
    for (int mi = 0; mi < 2; mi++)
#pragma unroll
        for (int ni = 0; ni < 12; ni++)
#pragma unroll
            for (int j = 0; j < 4; j++) acc[mi][ni][j] = 0.f;

    const int ar = tid >> 3;                 // A row for this thread's LDG/STS
    const int ak = (tid & 7) << 2;           // k4 offset
    float4 apf[4], wpf[6];

    // Prefetch chunk 0
#pragma unroll
    for (int j = 0; j < 4; j++) {
        int r = ar + j * 32;
        apf[j] = *(const float4*)(Ablk + (size_t)r * CDIM + ak);
    }
#pragma unroll
    for (int j = 0; j < 6; j++) {
        int r = ar + j * 32;
        wpf[j] = *(const float4*)(Wblk + (size_t)r * CDIM + ak);
    }
    // Store chunk 0 -> stage 0
    {
        float* sA = sm;
        float* sW = sm + 2 * ASZ;
#pragma unroll
        for (int j = 0; j < 4; j++) {
            int r = ar + j * 32;
            sA[r * APADW + ak + 0] = __uint_as_float(f2tf32(apf[j].x));
            sA[r * APADW + ak + 1] = __uint_as_float(f2tf32(apf[j].y));
            sA[r * APADW + ak + 2] = __uint_as_float(f2tf32(apf[j].z));
            sA[r * APADW + ak + 3] = __uint_as_float(f2tf32(apf[j].w));
        }
#pragma unroll
        for (int j = 0; j < 6; j++) {
            int r = ar + j * 32;
            sW[r * APADW + ak + 0] = __uint_as_float(f2tf32(wpf[j].x));
            sW[r * APADW + ak + 1] = __uint_as_float(f2tf32(wpf[j].y));
            sW[r * APADW + ak + 2] = __uint_as_float(f2tf32(wpf[j].z));
            sW[r * APADW + ak + 3] = __uint_as_float(f2tf32(wpf[j].w));
        }
    }
    __syncthreads();

#pragma unroll 1
    for (int c = 0; c < 6; c++) {
        const int st = c & 1;
        // Prefetch next chunk (global -> regs)
        if (c < 5) {
            const int ko = (c + 1) * GBK;
#pragma unroll
            for (int j = 0; j < 4; j++) {
                int r = ar + j * 32;
                apf[j] = *(const float4*)(Ablk + (size_t)r * CDIM + ko + ak);
            }
#pragma unroll
            for (int j = 0; j < 6; j++) {
                int r = ar + j * 32;
                wpf[j] = *(const float4*)(Wblk + (size_t)r * CDIM + ko + ak);
            }
        }

        // Compute on stage st
        {
            const float* sA = sm + st * ASZ;
            const float* sW = sm + 2 * ASZ + st * BSZ;
#pragma unroll
            for (int kk = 0; kk < 4; kk++) {
                const int k0 = kk * 8;
                uint32_t afr[2][4];
#pragma unroll
                for (int mi = 0; mi < 2; mi++) {
                    const int m = wm * 32 + mi * 16 + gid;
                    afr[mi][0] = __float_as_uint(sA[(m    ) * APADW + k0 + tc    ]);
                    afr[mi][1] = __float_as_uint(sA[(m + 8) * APADW + k0 + tc    ]);
                    afr[mi][2] = __float_as_uint(sA[(m    ) * APADW + k0 + tc + 4]);
                    afr[mi][3] = __float_as_uint(sA[(m + 8) * APADW + k0 + tc + 4]);
                }
#pragma unroll
                for (int ni = 0; ni < 12; ni++) {
                    const int n = wn * 96 + ni * 8 + gid;
                    uint32_t b0 = __float_as_uint(sW[n * APADW + k0 + tc    ]);
                    uint32_t b1 = __float_as_uint(sW[n * APADW + k0 + tc + 4]);
                    mma_tf32(acc[0][ni], afr[0], b0, b1);
                    mma_tf32(acc[1][ni], afr[1], b0, b1);
                }
            }
        }

        // Store prefetched chunk into the other stage (read-safe: all warps
        // finished reading it before the previous __syncthreads)
        if (c < 5) {
            float* sA = sm + (st ^ 1) * ASZ;
            float* sW = sm + 2 * ASZ + (st ^ 1) * BSZ;
#pragma unroll
            for (int j = 0; j < 4; j++) {
                int r = ar + j * 32;
                sA[r * APADW + ak + 0] = __uint_as_float(f2tf32(apf[j].x));
                sA[r * APADW + ak + 1] = __uint_as_float(f2tf32(apf[j].y));
                sA[r * APADW + ak + 2] = __uint_as_float(f2tf32(apf[j].z));
                sA[r * APADW + ak + 3] = __uint_as_float(f2tf32(apf[j].w));
            }
#pragma unroll
            for (int j = 0; j < 6; j++) {
                int r = ar + j * 32;
                sW[r * APADW + ak + 0] = __uint_as_float(f2tf32(wpf[j].x));
                sW[r * APADW + ak + 1] = __uint_as_float(f2tf32(wpf[j].y));
                sW[r * APADW + ak + 2] = __uint_as_float(f2tf32(wpf[j].z));
                sW[r * APADW + ak + 3] = __uint_as_float(f2tf32(wpf[j].w));
            }
            __syncthreads();
        }
    }

    // Epilogue: bias + direct float2 stores
    // c-fragment m16n8: d0,d1 at (row=gid, col=tc*2 {,+1}); d2,d3 at row=gid+8
#pragma unroll
    for (int mi = 0; mi < 2; mi++) {
#pragma unroll
        for (int ni = 0; ni < 12; ni++) {
            const size_t row = mbase + wm * 32 + mi * 16 + gid;
            const int    col = nbase + wn * 96 + ni * 8 + tc * 2;
            const float2 bb = *(const float2*)&bias[col];
            float2 r0, r1;
            r0.x = acc[mi][ni][0] + bb.x; r0.y = acc[mi][ni][1] + bb.y;
            r1.x = acc[mi][ni][2] + bb.x; r1.y = acc[mi][ni][3] + bb.y;
            *(float2*)&out[(row    ) * NCTOT + col] = r0;
            *(float2*)&out[(row + 8) * NCTOT + col] = r1;
        }
    }
}

// ---------------------------------------------------------------------------
// Fused attention (unchanged SIMT fp32): one block per (b, t, h)
// ---------------------------------------------------------------------------
__global__ __launch_bounds__(128) void attn_kernel(
    const float* __restrict__ Q, const float* __restrict__ KV,
    const float* __restrict__ rpb, float* __restrict__ O)
{
    const int blk = blockIdx.x;
    const int h   = blk % NHEAD;
    const int bt  = blk / NHEAD;
    const int b   = bt / TT;

    __shared__ float qs[NTOK][HDIM];
    __shared__ float ks[NTOK][HDIM + 1];
    __shared__ float vs[NTOK][HDIM + 1];
    __shared__ float S [NTOK][53];

    const int tid = threadIdx.x;

    for (int i = tid; i < NTOK * 8; i += 128) {
        int n  = i >> 3;
        int c4 = (i & 7) << 2;
        float4 q = *(const float4*)&Q[((size_t)(b * NTOK + n)) * CDIM + h * HDIM + c4];
        qs[n][c4 + 0] = q.x; qs[n][c4 + 1] = q.y; qs[n][c4 + 2] = q.z; qs[n][c4 + 3] = q.w;
        size_t kvbase = (size_t)(bt * NTOK + n) * (2 * CDIM) + h * HDIM + c4;
        float4 k = *(const float4*)&KV[kvbase];
        ks[n][c4 + 0] = k.x; ks[n][c4 + 1] = k.y; ks[n][c4 + 2] = k.z; ks[n][c4 + 3] = k.w;
        float4 v = *(const float4*)&KV[kvbase + CDIM];
        vs[n][c4 + 0] = v.x; vs[n][c4 + 1] = v.y; vs[n][c4 + 2] = v.z; vs[n][c4 + 3] = v.w;
    }
    __syncthreads();

    const float scale = 0.17677669529663687f;

    for (int idx = tid; idx < NTOK * NTOK; idx += 128) {
        int n = idx / NTOK, m = idx % NTOK;
        float acc = 0.f;
#pragma unroll
        for (int k = 0; k < HDIM; k++) acc += qs[n][k] * ks[m][k];
        int nh = n / 7, nw = n % 7, mh = m / 7, mw = m % 7;
        int ridx = (nh - mh + 6) * 13 + (nw - mw + 6);
        S[n][m] = acc * scale + rpb[ridx * NHEAD + h];
    }
    __syncthreads();

    if (tid < NTOK) {
        int n = tid;
        float mx = -1e30f;
#pragma unroll
        for (int m = 0; m < NTOK; m++) mx = fmaxf(mx, S[n][m]);
        float sum = 0.f;
#pragma unroll
        for (int m = 0; m < NTOK; m++) { float e = __expf(S[n][m] - mx); S[n][m] = e; sum += e; }
        float inv = 1.f / sum;
#pragma unroll
        for (int m = 0; m < NTOK; m++) S[n][m] *= inv;
    }
    __syncthreads();

    for (int idx = tid; idx < NTOK * HDIM; idx += 128) {
        int n = idx >> 5, dd = idx & 31;
        float acc = 0.f;
#pragma unroll
        for (int m = 0; m < NTOK; m++) acc += S[n][m] * vs[m][dd];
        O[(size_t)(bt * NTOK + n) * CDIM + h * HDIM + dd] = acc;
    }
}

// ---------------------------------------------------------------------------
// kernel_launch
// ---------------------------------------------------------------------------
extern "C" void kernel_launch(void* const* d_in, const int* in_sizes, int n_in,
                              void* d_out, int out_size)
{
    const float* x      = (const float*)d_in[0];
    const float* memory = (const float*)d_in[1];
    const float* w_q    = (const float*)d_in[2];
    const float* b_q    = (const float*)d_in[3];
    const float* w_kv   = (const float*)d_in[4];
    const float* b_kv   = (const float*)d_in[5];
    const float* w_proj = (const float*)d_in[6];
    const float* b_proj = (const float*)d_in[7];
    const float* rpb    = (const float*)d_in[8];
    float* out = (float*)d_out;

    float *gq, *gkv, *gao;
    cudaGetSymbolAddress((void**)&gq,  g_q);
    cudaGetSymbolAddress((void**)&gkv, g_kv);
    cudaGetSymbolAddress((void**)&gao, g_ao);

    const int SMEM = (2 * ASZ + 2 * BSZ) * 4;   // 92160 bytes
    cudaFuncSetAttribute(gemm_mma<192>, cudaFuncAttributeMaxDynamicSharedMemorySize, SMEM);
    cudaFuncSetAttribute(gemm_mma<384>, cudaFuncAttributeMaxDynamicSharedMemorySize, SMEM);

    // Q projection: [200704 x 192] @ [192 x 192]^T
    gemm_mma<192><<<dim3(M_Q / 128, 1), 256, SMEM>>>(x, w_q, b_q, gq);
    // KV projection: [401408 x 192] @ [384 x 192]^T (2 column blocks)
    gemm_mma<384><<<dim3(M_KV / 128, 2), 256, SMEM>>>(memory, w_kv, b_kv, gkv);
    // Fused attention per (b, t, h)
    attn_kernel<<<BATCH * TT * NHEAD, 128>>>(gq, gkv, rpb, gao);
    // Output projection: [401408 x 192] @ [192 x 192]^T -> d_out
    gemm_mma<192><<<dim3(M_KV / 128, 1), 256, SMEM>>>(gao, w_proj, b_proj, out);
}

// round 7
// speedup vs baseline: 2.5061x; 1.3459x over previous
#include <cuda_runtime.h>
#include <cstdint>
#include <cstddef>

// ---------------------------------------------------------------------------
// Problem constants
// ---------------------------------------------------------------------------
#define BATCH   4096
#define TT      2
#define NTOK    49
#define CDIM    192
#define NHEAD   6
#define HDIM    32

#define M_Q   (BATCH * NTOK)          // 200704
#define M_KV  (BATCH * TT * NTOK)     // 401408

// Scratch (device globals: allocation-free rule)
__device__ float g_q [(size_t)M_Q  * CDIM];
__device__ float g_kv[(size_t)M_KV * 2 * CDIM];
__device__ float g_ao[(size_t)M_KV * CDIM];

// ---------------------------------------------------------------------------
// Helpers
// ---------------------------------------------------------------------------
__device__ __forceinline__ uint32_t f2tf32(float f) {   // round-to-nearest tf32
    uint32_t u;
    asm("cvt.rna.tf32.f32 %0, %1;" : "=r"(u) : "f"(f));
    return u;
}
__device__ __forceinline__ float tfv(float f) { return __uint_as_float(f2tf32(f)); }
__device__ __forceinline__ void mma_tf32(float* d, const uint32_t* a,
                                         uint32_t b0, uint32_t b1) {
    asm volatile(
        "mma.sync.aligned.m16n8k8.row.col.f32.tf32.tf32.f32 "
        "{%0,%1,%2,%3}, {%4,%5,%6,%7}, {%8,%9}, {%0,%1,%2,%3};"
        : "+f"(d[0]), "+f"(d[1]), "+f"(d[2]), "+f"(d[3])
        : "r"(a[0]), "r"(a[1]), "r"(a[2]), "r"(a[3]), "r"(b0), "r"(b1));
}

// ---------------------------------------------------------------------------
// Tensor-core GEMM via mma.sync tf32 (unchanged from R6)
// ---------------------------------------------------------------------------
#define GBK   32
#define APADW 36
#define ASZ   (128 * APADW)
#define BSZ   (192 * APADW)

template<int NCTOT>
__global__ __launch_bounds__(256, 1)
void gemm_mma(const float* __restrict__ A, const float* __restrict__ W,
              const float* __restrict__ bias, float* __restrict__ out)
{
    extern __shared__ float sm[];
    const int tid  = threadIdx.x;
    const int wid  = tid >> 5;
    const int lane = tid & 31;
    const int wm   = wid & 3;
    const int wn   = wid >> 2;
    const int gid  = lane >> 2;
    const int tc   = lane & 3;

    const size_t mbase = (size_t)blockIdx.x * 128;
    const int    nbase = blockIdx.y * 192;
    const float* Ablk = A + mbase * CDIM;
    const float* Wblk = W + (size_t)nbase * CDIM;

    float acc[2][12][4];
#pragma unroll
    for (int mi = 0; mi < 2; mi++)
#pragma unroll
        for (int ni = 0; ni < 12; ni++)
#pragma unroll
            for (int j = 0; j < 4; j++) acc[mi][ni][j] = 0.f;

    const int ar = tid >> 3;
    const int ak = (tid & 7) << 2;
    float4 apf[4], wpf[6];

#pragma unroll
    for (int j = 0; j < 4; j++) {
        int r = ar + j * 32;
        apf[j] = *(const float4*)(Ablk + (size_t)r * CDIM + ak);
    }
#pragma unroll
    for (int j = 0; j < 6; j++) {
        int r = ar + j * 32;
        wpf[j] = *(const float4*)(Wblk + (size_t)r * CDIM + ak);
    }
    {
        float* sA = sm;
        float* sW = sm + 2 * ASZ;
#pragma unroll
        for (int j = 0; j < 4; j++) {
            int r = ar + j * 32;
            sA[r * APADW + ak + 0] = tfv(apf[j].x);
            sA[r * APADW + ak + 1] = tfv(apf[j].y);
            sA[r * APADW + ak + 2] = tfv(apf[j].z);
            sA[r * APADW + ak + 3] = tfv(apf[j].w);
        }
#pragma unroll
        for (int j = 0; j < 6; j++) {
            int r = ar + j * 32;
            sW[r * APADW + ak + 0] = tfv(wpf[j].x);
            sW[r * APADW + ak + 1] = tfv(wpf[j].y);
            sW[r * APADW + ak + 2] = tfv(wpf[j].z);
            sW[r * APADW + ak + 3] = tfv(wpf[j].w);
        }
    }
    __syncthreads();

#pragma unroll 1
    for (int c = 0; c < 6; c++) {
        const int st = c & 1;
        if (c < 5) {
            const int ko = (c + 1) * GBK;
#pragma unroll
            for (int j = 0; j < 4; j++) {
                int r = ar + j * 32;
                apf[j] = *(const float4*)(Ablk + (size_t)r * CDIM + ko + ak);
            }
#pragma unroll
            for (int j = 0; j < 6; j++) {
                int r = ar + j * 32;
                wpf[j] = *(const float4*)(Wblk + (size_t)r * CDIM + ko + ak);
            }
        }
        {
            const float* sA = sm + st * ASZ;
            const float* sW = sm + 2 * ASZ + st * BSZ;
#pragma unroll
            for (int kk = 0; kk < 4; kk++) {
                const int k0 = kk * 8;
                uint32_t afr[2][4];
#pragma unroll
                for (int mi = 0; mi < 2; mi++) {
                    const int m = wm * 32 + mi * 16 + gid;
                    afr[mi][0] = __float_as_uint(sA[(m    ) * APADW + k0 + tc    ]);
                    afr[mi][1] = __float_as_uint(sA[(m + 8) * APADW + k0 + tc    ]);
                    afr[mi][2] = __float_as_uint(sA[(m    ) * APADW + k0 + tc + 4]);
                    afr[mi][3] = __float_as_uint(sA[(m + 8) * APADW + k0 + tc + 4]);
                }
#pragma unroll
                for (int ni = 0; ni < 12; ni++) {
                    const int n = wn * 96 + ni * 8 + gid;
                    uint32_t b0 = __float_as_uint(sW[n * APADW + k0 + tc    ]);
                    uint32_t b1 = __float_as_uint(sW[n * APADW + k0 + tc + 4]);
                    mma_tf32(acc[0][ni], afr[0], b0, b1);
                    mma_tf32(acc[1][ni], afr[1], b0, b1);
                }
            }
        }
        if (c < 5) {
            float* sA = sm + (st ^ 1) * ASZ;
            float* sW = sm + 2 * ASZ + (st ^ 1) * BSZ;
#pragma unroll
            for (int j = 0; j < 4; j++) {
                int r = ar + j * 32;
                sA[r * APADW + ak + 0] = tfv(apf[j].x);
                sA[r * APADW + ak + 1] = tfv(apf[j].y);
                sA[r * APADW + ak + 2] = tfv(apf[j].z);
                sA[r * APADW + ak + 3] = tfv(apf[j].w);
            }
#pragma unroll
            for (int j = 0; j < 6; j++) {
                int r = ar + j * 32;
                sW[r * APADW + ak + 0] = tfv(wpf[j].x);
                sW[r * APADW + ak + 1] = tfv(wpf[j].y);
                sW[r * APADW + ak + 2] = tfv(wpf[j].z);
                sW[r * APADW + ak + 3] = tfv(wpf[j].w);
            }
            __syncthreads();
        }
    }

#pragma unroll
    for (int mi = 0; mi < 2; mi++) {
#pragma unroll
        for (int ni = 0; ni < 12; ni++) {
            const size_t row = mbase + wm * 32 + mi * 16 + gid;
            const int    col = nbase + wn * 96 + ni * 8 + tc * 2;
            const float2 bb = *(const float2*)&bias[col];
            float2 r0, r1;
            r0.x = acc[mi][ni][0] + bb.x; r0.y = acc[mi][ni][1] + bb.y;
            r1.x = acc[mi][ni][2] + bb.x; r1.y = acc[mi][ni][3] + bb.y;
            *(float2*)&out[(row    ) * NCTOT + col] = r0;
            *(float2*)&out[(row + 8) * NCTOT + col] = r1;
        }
    }
}

// ---------------------------------------------------------------------------
// Tensor-core attention: one CTA per (b,t), one warp per head, warp-local.
// QK^T and PV via mma.sync tf32; softmax + relative-position bias in smem.
// Bias idx is separable: ridx = f(n) - f(m) + 84, f(t) = 13*(t/7) + t%7.
// ---------------------------------------------------------------------------
#define QKV_PAD 36
#define S_PAD   58
#define HEADF   (3 * NTOK * QKV_PAD + NTOK * S_PAD)   // 8134 floats per head
#define ATTN_SMEM ((6 * HEADF + 6 * 169) * 4)         // 199272 bytes

__global__ __launch_bounds__(192, 1)
void attn_mma(const float* __restrict__ Q, const float* __restrict__ KV,
              const float* __restrict__ rpb, float* __restrict__ O)
{
    extern __shared__ float sm[];
    const int wid  = threadIdx.x >> 5;     // head
    const int lane = threadIdx.x & 31;
    const int gid  = lane >> 2;
    const int tc   = lane & 3;
    const int bt   = blockIdx.x;
    const int b    = bt >> 1;
    const int h    = wid;

    float* sQ = sm + wid * HEADF;
    float* sK = sQ + NTOK * QKV_PAD;
    float* sV = sK + NTOK * QKV_PAD;
    float* sS = sV + NTOK * QKV_PAD;
    float* srpb = sm + 6 * HEADF + wid * 169;

    // Per-head rpb slice
    for (int i = lane; i < 169; i += 32) srpb[i] = rpb[i * NHEAD + h];

    const float scale = 0.17677669529663687f;
    // Load Q (x scale), K, V head slices as tf32 values
    for (int i = lane; i < NTOK * 8; i += 32) {
        int n = i >> 3, c4 = (i & 7) << 2;
        float4 q = *(const float4*)&Q[((size_t)(b * NTOK + n)) * CDIM + h * HDIM + c4];
        sQ[n * QKV_PAD + c4 + 0] = tfv(q.x * scale);
        sQ[n * QKV_PAD + c4 + 1] = tfv(q.y * scale);
        sQ[n * QKV_PAD + c4 + 2] = tfv(q.z * scale);
        sQ[n * QKV_PAD + c4 + 3] = tfv(q.w * scale);
        size_t kb = (size_t)(bt * NTOK + n) * (2 * CDIM) + h * HDIM + c4;
        float4 k = *(const float4*)&KV[kb];
        sK[n * QKV_PAD + c4 + 0] = tfv(k.x);
        sK[n * QKV_PAD + c4 + 1] = tfv(k.y);
        sK[n * QKV_PAD + c4 + 2] = tfv(k.z);
        sK[n * QKV_PAD + c4 + 3] = tfv(k.w);
        float4 v = *(const float4*)&KV[kb + CDIM];
        sV[n * QKV_PAD + c4 + 0] = tfv(v.x);
        sV[n * QKV_PAD + c4 + 1] = tfv(v.y);
        sV[n * QKV_PAD + c4 + 2] = tfv(v.z);
        sV[n * QKV_PAD + c4 + 3] = tfv(v.w);
    }
    __syncwarp();

    // Guarded row indices (pad rows clamp to 48; results unused / multiplied by 0)
    int mr[4][2], nr[7];
#pragma unroll
    for (int mi = 0; mi < 4; mi++) {
        mr[mi][0] = min(16 * mi + gid, 48);
        mr[mi][1] = min(16 * mi + gid + 8, 48);
    }
#pragma unroll
    for (int ni = 0; ni < 7; ni++) nr[ni] = min(8 * ni + gid, 48);

    // ---- S = (Q*scale) K^T ----
    float sf[4][7][4];
#pragma unroll
    for (int mi = 0; mi < 4; mi++)
#pragma unroll
        for (int ni = 0; ni < 7; ni++)
#pragma unroll
            for (int j = 0; j < 4; j++) sf[mi][ni][j] = 0.f;

#pragma unroll
    for (int kk = 0; kk < 4; kk++) {
        const int k0 = kk * 8;
        uint32_t a[4][4];
#pragma unroll
        for (int mi = 0; mi < 4; mi++) {
            a[mi][0] = __float_as_uint(sQ[mr[mi][0] * QKV_PAD + k0 + tc    ]);
            a[mi][1] = __float_as_uint(sQ[mr[mi][1] * QKV_PAD + k0 + tc    ]);
            a[mi][2] = __float_as_uint(sQ[mr[mi][0] * QKV_PAD + k0 + tc + 4]);
            a[mi][3] = __float_as_uint(sQ[mr[mi][1] * QKV_PAD + k0 + tc + 4]);
        }
#pragma unroll
        for (int ni = 0; ni < 7; ni++) {
            uint32_t b0 = __float_as_uint(sK[nr[ni] * QKV_PAD + k0 + tc    ]);
            uint32_t b1 = __float_as_uint(sK[nr[ni] * QKV_PAD + k0 + tc + 4]);
#pragma unroll
            for (int mi = 0; mi < 4; mi++) mma_tf32(sf[mi][ni], a[mi], b0, b1);
        }
    }
    // Store S (rows < 49 only, raw; bias added in softmax pass)
#pragma unroll
    for (int mi = 0; mi < 4; mi++) {
        const int r0 = 16 * mi + gid;
#pragma unroll
        for (int ni = 0; ni < 7; ni++) {
            const int col = 8 * ni + 2 * tc;
            if (r0 < NTOK) {
                sS[r0 * S_PAD + col]     = sf[mi][ni][0];
                sS[r0 * S_PAD + col + 1] = sf[mi][ni][1];
            }
            if (r0 + 8 < NTOK) {
                sS[(r0 + 8) * S_PAD + col]     = sf[mi][ni][2];
                sS[(r0 + 8) * S_PAD + col + 1] = sf[mi][ni][3];
            }
        }
    }
    __syncwarp();

    // ---- softmax (bias folded in), one row per lane ----
#pragma unroll
    for (int rep = 0; rep < 2; rep++) {
        const int n = lane + rep * 32;
        if (n < NTOK) {
            float* row = sS + n * S_PAD;
            const float* bp = srpb + (n / 7) * 13 + (n % 7) + 84;
            float mx = -1e30f;
#pragma unroll
            for (int m = 0; m < NTOK; m++) {
                float v = row[m] + bp[-((m / 7) * 13 + (m % 7))];
                row[m] = v;
                mx = fmaxf(mx, v);
            }
            float sum = 0.f;
#pragma unroll
            for (int m = 0; m < NTOK; m++) {
                float e = __expf(row[m] - mx);
                row[m] = e;
                sum += e;
            }
            const float inv = 1.f / sum;
#pragma unroll
            for (int m = 0; m < NTOK; m++) row[m] = tfv(row[m] * inv);
#pragma unroll
            for (int m = NTOK; m < 56; m++) row[m] = 0.f;   // pad cols -> 0
        }
    }
    __syncwarp();

    // ---- O = P V ----
    float of[4][4][4];
#pragma unroll
    for (int mi = 0; mi < 4; mi++)
#pragma unroll
        for (int nd = 0; nd < 4; nd++)
#pragma unroll
            for (int j = 0; j < 4; j++) of[mi][nd][j] = 0.f;

#pragma unroll
    for (int kk = 0; kk < 7; kk++) {
        const int k0 = kk * 8;
        uint32_t a[4][4];
#pragma unroll
        for (int mi = 0; mi < 4; mi++) {
            a[mi][0] = __float_as_uint(sS[mr[mi][0] * S_PAD + k0 + tc    ]);
            a[mi][1] = __float_as_uint(sS[mr[mi][1] * S_PAD + k0 + tc    ]);
            a[mi][2] = __float_as_uint(sS[mr[mi][0] * S_PAD + k0 + tc + 4]);
            a[mi][3] = __float_as_uint(sS[mr[mi][1] * S_PAD + k0 + tc + 4]);
        }
        const int bm0 = min(k0 + tc, 48);        // P cols >= 49 are zero
        const int bm1 = min(k0 + tc + 4, 48);
#pragma unroll
        for (int nd = 0; nd < 4; nd++) {
            uint32_t b0 = __float_as_uint(sV[bm0 * QKV_PAD + nd * 8 + gid]);
            uint32_t b1 = __float_as_uint(sV[bm1 * QKV_PAD + nd * 8 + gid]);
#pragma unroll
            for (int mi = 0; mi < 4; mi++) mma_tf32(of[mi][nd], a[mi], b0, b1);
        }
    }
    // Store O head slice
#pragma unroll
    for (int mi = 0; mi < 4; mi++) {
        const int r0 = 16 * mi + gid;
#pragma unroll
        for (int nd = 0; nd < 4; nd++) {
            const int col = h * HDIM + nd * 8 + 2 * tc;
            if (r0 < NTOK) {
                float2 o = {of[mi][nd][0], of[mi][nd][1]};
                *(float2*)&O[((size_t)(bt * NTOK + r0)) * CDIM + col] = o;
            }
            if (r0 + 8 < NTOK) {
                float2 o = {of[mi][nd][2], of[mi][nd][3]};
                *(float2*)&O[((size_t)(bt * NTOK + r0 + 8)) * CDIM + col] = o;
            }
        }
    }
}

// ---------------------------------------------------------------------------
// kernel_launch
// ---------------------------------------------------------------------------
extern "C" void kernel_launch(void* const* d_in, const int* in_sizes, int n_in,
                              void* d_out, int out_size)
{
    const float* x      = (const float*)d_in[0];
    const float* memory = (const float*)d_in[1];
    const float* w_q    = (const float*)d_in[2];
    const float* b_q    = (const float*)d_in[3];
    const float* w_kv   = (const float*)d_in[4];
    const float* b_kv   = (const float*)d_in[5];
    const float* w_proj = (const float*)d_in[6];
    const float* b_proj = (const float*)d_in[7];
    const float* rpb    = (const float*)d_in[8];
    float* out = (float*)d_out;

    float *gq, *gkv, *gao;
    cudaGetSymbolAddress((void**)&gq,  g_q);
    cudaGetSymbolAddress((void**)&gkv, g_kv);
    cudaGetSymbolAddress((void**)&gao, g_ao);

    const int SMEM = (2 * ASZ + 2 * BSZ) * 4;
    cudaFuncSetAttribute(gemm_mma<192>, cudaFuncAttributeMaxDynamicSharedMemorySize, SMEM);
    cudaFuncSetAttribute(gemm_mma<384>, cudaFuncAttributeMaxDynamicSharedMemorySize, SMEM);
    cudaFuncSetAttribute(attn_mma, cudaFuncAttributeMaxDynamicSharedMemorySize, ATTN_SMEM);

    // Q projection
    gemm_mma<192><<<dim3(M_Q / 128, 1), 256, SMEM>>>(x, w_q, b_q, gq);
    // KV projection
    gemm_mma<384><<<dim3(M_KV / 128, 2), 256, SMEM>>>(memory, w_kv, b_kv, gkv);
    // Tensor-core attention, one CTA per (b,t)
    attn_mma<<<BATCH * TT, 192, ATTN_SMEM>>>(gq, gkv, rpb, gao);
    // Output projection
    gemm_mma<192><<<dim3(M_KV / 128, 1), 256, SMEM>>>(gao, w_proj, b_proj, out);
}

// round 8
// speedup vs baseline: 3.0044x; 1.1988x over previous
#include <cuda_runtime.h>
#include <cstdint>
#include <cstddef>

// ---------------------------------------------------------------------------
// Problem constants
// ---------------------------------------------------------------------------
#define BATCH   4096
#define TT      2
#define NTOK    49
#define CDIM    192
#define NHEAD   6
#define HDIM    32

#define M_Q   (BATCH * NTOK)          // 200704
#define M_KV  (BATCH * TT * NTOK)     // 401408

// Scratch (device globals: allocation-free rule)
__device__ float g_q [(size_t)M_Q  * CDIM];
__device__ float g_kv[(size_t)M_KV * 2 * CDIM];
__device__ float g_ao[(size_t)M_KV * CDIM];

// ---------------------------------------------------------------------------
// Helpers
// ---------------------------------------------------------------------------
__device__ __forceinline__ uint32_t f2tf32(float f) {   // round-to-nearest tf32
    uint32_t u;
    asm("cvt.rna.tf32.f32 %0, %1;" : "=r"(u) : "f"(f));
    return u;
}
__device__ __forceinline__ float tfv(float f) { return __uint_as_float(f2tf32(f)); }
__device__ __forceinline__ void mma_tf32(float* d, const uint32_t* a,
                                         uint32_t b0, uint32_t b1) {
    asm volatile(
        "mma.sync.aligned.m16n8k8.row.col.f32.tf32.tf32.f32 "
        "{%0,%1,%2,%3}, {%4,%5,%6,%7}, {%8,%9}, {%0,%1,%2,%3};"
        : "+f"(d[0]), "+f"(d[1]), "+f"(d[2]), "+f"(d[3])
        : "r"(a[0]), "r"(a[1]), "r"(a[2]), "r"(a[3]), "r"(b0), "r"(b1));
}

// ---------------------------------------------------------------------------
// Tensor-core GEMM via mma.sync tf32 (unchanged from R6/R7)
// ---------------------------------------------------------------------------
#define GBK   32
#define APADW 36
#define ASZ   (128 * APADW)
#define BSZ   (192 * APADW)

template<int NCTOT>
__global__ __launch_bounds__(256, 1)
void gemm_mma(const float* __restrict__ A, const float* __restrict__ W,
              const float* __restrict__ bias, float* __restrict__ out)
{
    extern __shared__ float sm[];
    const int tid  = threadIdx.x;
    const int wid  = tid >> 5;
    const int lane = tid & 31;
    const int wm   = wid & 3;
    const int wn   = wid >> 2;
    const int gid  = lane >> 2;
    const int tc   = lane & 3;

    const size_t mbase = (size_t)blockIdx.x * 128;
    const int    nbase = blockIdx.y * 192;
    const float* Ablk = A + mbase * CDIM;
    const float* Wblk = W + (size_t)nbase * CDIM;

    float acc[2][12][4];
#pragma unroll
    for (int mi = 0; mi < 2; mi++)
#pragma unroll
        for (int ni = 0; ni < 12; ni++)
#pragma unroll
            for (int j = 0; j < 4; j++) acc[mi][ni][j] = 0.f;

    const int ar = tid >> 3;
    const int ak = (tid & 7) << 2;
    float4 apf[4], wpf[6];

#pragma unroll
    for (int j = 0; j < 4; j++) {
        int r = ar + j * 32;
        apf[j] = *(const float4*)(Ablk + (size_t)r * CDIM + ak);
    }
#pragma unroll
    for (int j = 0; j < 6; j++) {
        int r = ar + j * 32;
        wpf[j] = *(const float4*)(Wblk + (size_t)r * CDIM + ak);
    }
    {
        float* sA = sm;
        float* sW = sm + 2 * ASZ;
#pragma unroll
        for (int j = 0; j < 4; j++) {
            int r = ar + j * 32;
            sA[r * APADW + ak + 0] = tfv(apf[j].x);
            sA[r * APADW + ak + 1] = tfv(apf[j].y);
            sA[r * APADW + ak + 2] = tfv(apf[j].z);
            sA[r * APADW + ak + 3] = tfv(apf[j].w);
        }
#pragma unroll
        for (int j = 0; j < 6; j++) {
            int r = ar + j * 32;
            sW[r * APADW + ak + 0] = tfv(wpf[j].x);
            sW[r * APADW + ak + 1] = tfv(wpf[j].y);
            sW[r * APADW + ak + 2] = tfv(wpf[j].z);
            sW[r * APADW + ak + 3] = tfv(wpf[j].w);
        }
    }
    __syncthreads();

#pragma unroll 1
    for (int c = 0; c < 6; c++) {
        const int st = c & 1;
        if (c < 5) {
            const int ko = (c + 1) * GBK;
#pragma unroll
            for (int j = 0; j < 4; j++) {
                int r = ar + j * 32;
                apf[j] = *(const float4*)(Ablk + (size_t)r * CDIM + ko + ak);
            }
#pragma unroll
            for (int j = 0; j < 6; j++) {
                int r = ar + j * 32;
                wpf[j] = *(const float4*)(Wblk + (size_t)r * CDIM + ko + ak);
            }
        }
        {
            const float* sA = sm + st * ASZ;
            const float* sW = sm + 2 * ASZ + st * BSZ;
#pragma unroll
            for (int kk = 0; kk < 4; kk++) {
                const int k0 = kk * 8;
                uint32_t afr[2][4];
#pragma unroll
                for (int mi = 0; mi < 2; mi++) {
                    const int m = wm * 32 + mi * 16 + gid;
                    afr[mi][0] = __float_as_uint(sA[(m    ) * APADW + k0 + tc    ]);
                    afr[mi][1] = __float_as_uint(sA[(m + 8) * APADW + k0 + tc    ]);
                    afr[mi][2] = __float_as_uint(sA[(m    ) * APADW + k0 + tc + 4]);
                    afr[mi][3] = __float_as_uint(sA[(m + 8) * APADW + k0 + tc + 4]);
                }
#pragma unroll
                for (int ni = 0; ni < 12; ni++) {
                    const int n = wn * 96 + ni * 8 + gid;
                    uint32_t b0 = __float_as_uint(sW[n * APADW + k0 + tc    ]);
                    uint32_t b1 = __float_as_uint(sW[n * APADW + k0 + tc + 4]);
                    mma_tf32(acc[0][ni], afr[0], b0, b1);
                    mma_tf32(acc[1][ni], afr[1], b0, b1);
                }
            }
        }
        if (c < 5) {
            float* sA = sm + (st ^ 1) * ASZ;
            float* sW = sm + 2 * ASZ + (st ^ 1) * BSZ;
#pragma unroll
            for (int j = 0; j < 4; j++) {
                int r = ar + j * 32;
                sA[r * APADW + ak + 0] = tfv(apf[j].x);
                sA[r * APADW + ak + 1] = tfv(apf[j].y);
                sA[r * APADW + ak + 2] = tfv(apf[j].z);
                sA[r * APADW + ak + 3] = tfv(apf[j].w);
            }
#pragma unroll
            for (int j = 0; j < 6; j++) {
                int r = ar + j * 32;
                sW[r * APADW + ak + 0] = tfv(wpf[j].x);
                sW[r * APADW + ak + 1] = tfv(wpf[j].y);
                sW[r * APADW + ak + 2] = tfv(wpf[j].z);
                sW[r * APADW + ak + 3] = tfv(wpf[j].w);
            }
            __syncthreads();
        }
    }

#pragma unroll
    for (int mi = 0; mi < 2; mi++) {
#pragma unroll
        for (int ni = 0; ni < 12; ni++) {
            const size_t row = mbase + wm * 32 + mi * 16 + gid;
            const int    col = nbase + wn * 96 + ni * 8 + tc * 2;
            const float2 bb = *(const float2*)&bias[col];
            float2 r0, r1;
            r0.x = acc[mi][ni][0] + bb.x; r0.y = acc[mi][ni][1] + bb.y;
            r1.x = acc[mi][ni][2] + bb.x; r1.y = acc[mi][ni][3] + bb.y;
            *(float2*)&out[(row    ) * NCTOT + col] = r0;
            *(float2*)&out[(row + 8) * NCTOT + col] = r1;
        }
    }
}

// ---------------------------------------------------------------------------
// Tensor-core attention: 2 heads per CTA (64 threads), one warp per head.
// S overlays the Q+K region (dead after the QK mma loop) -> 43.7KB smem/CTA,
// 5 CTAs/SM.  Bias idx separable: ridx = f(n) - f(m) + 84.
// ---------------------------------------------------------------------------
#define HPC     2
#define QKV_PAD 36
#define S_PAD   58
#define HEADF2  (3 * NTOK * QKV_PAD)                   // 5292 floats per head
#define ATTN_SMEM ((HPC * HEADF2 + HPC * 169) * 4)     // 43688 bytes

__global__ __launch_bounds__(HPC * 32, 1)
void attn_mma(const float* __restrict__ Q, const float* __restrict__ KV,
              const float* __restrict__ rpb, float* __restrict__ O)
{
    extern __shared__ float sm[];
    const int wid  = threadIdx.x >> 5;
    const int lane = threadIdx.x & 31;
    const int gid  = lane >> 2;
    const int tc   = lane & 3;
    const int bt   = blockIdx.x;
    const int b    = bt >> 1;
    const int h    = blockIdx.y * HPC + wid;

    float* sQ = sm + wid * HEADF2;
    float* sK = sQ + NTOK * QKV_PAD;
    float* sV = sK + NTOK * QKV_PAD;
    float* sS = sQ;                                    // overlay on Q+K
    float* srpb = sm + HPC * HEADF2 + wid * 169;

    for (int i = lane; i < 169; i += 32) srpb[i] = rpb[i * NHEAD + h];

    const float scale = 0.17677669529663687f;
    for (int i = lane; i < NTOK * 8; i += 32) {
        int n = i >> 3, c4 = (i & 7) << 2;
        float4 q = *(const float4*)&Q[((size_t)(b * NTOK + n)) * CDIM + h * HDIM + c4];
        sQ[n * QKV_PAD + c4 + 0] = tfv(q.x * scale);
        sQ[n * QKV_PAD + c4 + 1] = tfv(q.y * scale);
        sQ[n * QKV_PAD + c4 + 2] = tfv(q.z * scale);
        sQ[n * QKV_PAD + c4 + 3] = tfv(q.w * scale);
        size_t kb = (size_t)(bt * NTOK + n) * (2 * CDIM) + h * HDIM + c4;
        float4 k = *(const float4*)&KV[kb];
        sK[n * QKV_PAD + c4 + 0] = tfv(k.x);
        sK[n * QKV_PAD + c4 + 1] = tfv(k.y);
        sK[n * QKV_PAD + c4 + 2] = tfv(k.z);
        sK[n * QKV_PAD + c4 + 3] = tfv(k.w);
        float4 v = *(const float4*)&KV[kb + CDIM];
        sV[n * QKV_PAD + c4 + 0] = tfv(v.x);
        sV[n * QKV_PAD + c4 + 1] = tfv(v.y);
        sV[n * QKV_PAD + c4 + 2] = tfv(v.z);
        sV[n * QKV_PAD + c4 + 3] = tfv(v.w);
    }
    __syncwarp();

    int mr[4][2], nr[7];
#pragma unroll
    for (int mi = 0; mi < 4; mi++) {
        mr[mi][0] = min(16 * mi + gid, 48);
        mr[mi][1] = min(16 * mi + gid + 8, 48);
    }
#pragma unroll
    for (int ni = 0; ni < 7; ni++) nr[ni] = min(8 * ni + gid, 48);

    // ---- S = (Q*scale) K^T ----
    float sf[4][7][4];
#pragma unroll
    for (int mi = 0; mi < 4; mi++)
#pragma unroll
        for (int ni = 0; ni < 7; ni++)
#pragma unroll
            for (int j = 0; j < 4; j++) sf[mi][ni][j] = 0.f;

#pragma unroll
    for (int kk = 0; kk < 4; kk++) {
        const int k0 = kk * 8;
        uint32_t a[4][4];
#pragma unroll
        for (int mi = 0; mi < 4; mi++) {
            a[mi][0] = __float_as_uint(sQ[mr[mi][0] * QKV_PAD + k0 + tc    ]);
            a[mi][1] = __float_as_uint(sQ[mr[mi][1] * QKV_PAD + k0 + tc    ]);
            a[mi][2] = __float_as_uint(sQ[mr[mi][0] * QKV_PAD + k0 + tc + 4]);
            a[mi][3] = __float_as_uint(sQ[mr[mi][1] * QKV_PAD + k0 + tc + 4]);
        }
#pragma unroll
        for (int ni = 0; ni < 7; ni++) {
            uint32_t b0 = __float_as_uint(sK[nr[ni] * QKV_PAD + k0 + tc    ]);
            uint32_t b1 = __float_as_uint(sK[nr[ni] * QKV_PAD + k0 + tc + 4]);
#pragma unroll
            for (int mi = 0; mi < 4; mi++) mma_tf32(sf[mi][ni], a[mi], b0, b1);
        }
    }
    __syncwarp();     // all Q/K fragment reads done before S overlays them

    // Store S (rows < 49 only)
#pragma unroll
    for (int mi = 0; mi < 4; mi++) {
        const int r0 = 16 * mi + gid;
#pragma unroll
        for (int ni = 0; ni < 7; ni++) {
            const int col = 8 * ni + 2 * tc;
            if (r0 < NTOK) {
                sS[r0 * S_PAD + col]     = sf[mi][ni][0];
                sS[r0 * S_PAD + col + 1] = sf[mi][ni][1];
            }
            if (r0 + 8 < NTOK) {
                sS[(r0 + 8) * S_PAD + col]     = sf[mi][ni][2];
                sS[(r0 + 8) * S_PAD + col + 1] = sf[mi][ni][3];
            }
        }
    }
    __syncwarp();

    // ---- softmax (bias folded in), one row per lane ----
#pragma unroll
    for (int rep = 0; rep < 2; rep++) {
        const int n = lane + rep * 32;
        if (n < NTOK) {
            float* row = sS + n * S_PAD;
            const float* bp = srpb + (n / 7) * 13 + (n % 7) + 84;
            float mx = -1e30f;
#pragma unroll
            for (int m = 0; m < NTOK; m++) {
                float v = row[m] + bp[-((m / 7) * 13 + (m % 7))];
                row[m] = v;
                mx = fmaxf(mx, v);
            }
            float sum = 0.f;
#pragma unroll
            for (int m = 0; m < NTOK; m++) {
                float e = __expf(row[m] - mx);
                row[m] = e;
                sum += e;
            }
            const float inv = 1.f / sum;
#pragma unroll
            for (int m = 0; m < NTOK; m++) row[m] = tfv(row[m] * inv);
#pragma unroll
            for (int m = NTOK; m < 56; m++) row[m] = 0.f;   // pad cols -> 0
        }
    }
    __syncwarp();

    // ---- O = P V ----
    float of[4][4][4];
#pragma unroll
    for (int mi = 0; mi < 4; mi++)
#pragma unroll
        for (int nd = 0; nd < 4; nd++)
#pragma unroll
            for (int j = 0; j < 4; j++) of[mi][nd][j] = 0.f;

#pragma unroll
    for (int kk = 0; kk < 7; kk++) {
        const int k0 = kk * 8;
        uint32_t a[4][4];
#pragma unroll
        for (int mi = 0; mi < 4; mi++) {
            a[mi][0] = __float_as_uint(sS[mr[mi][0] * S_PAD + k0 + tc    ]);
            a[mi][1] = __float_as_uint(sS[mr[mi][1] * S_PAD + k0 + tc    ]);
            a[mi][2] = __float_as_uint(sS[mr[mi][0] * S_PAD + k0 + tc + 4]);
            a[mi][3] = __float_as_uint(sS[mr[mi][1] * S_PAD + k0 + tc + 4]);
        }
        const int bm0 = min(k0 + tc, 48);        // P cols >= 49 are zero
        const int bm1 = min(k0 + tc + 4, 48);
#pragma unroll
        for (int nd = 0; nd < 4; nd++) {
            uint32_t b0 = __float_as_uint(sV[bm0 * QKV_PAD + nd * 8 + gid]);
            uint32_t b1 = __float_as_uint(sV[bm1 * QKV_PAD + nd * 8 + gid]);
#pragma unroll
            for (int mi = 0; mi < 4; mi++) mma_tf32(of[mi][nd], a[mi], b0, b1);
        }
    }
#pragma unroll
    for (int mi = 0; mi < 4; mi++) {
        const int r0 = 16 * mi + gid;
#pragma unroll
        for (int nd = 0; nd < 4; nd++) {
            const int col = h * HDIM + nd * 8 + 2 * tc;
            if (r0 < NTOK) {
                float2 o = {of[mi][nd][0], of[mi][nd][1]};
                *(float2*)&O[((size_t)(bt * NTOK + r0)) * CDIM + col] = o;
            }
            if (r0 + 8 < NTOK) {
                float2 o = {of[mi][nd][2], of[mi][nd][3]};
                *(float2*)&O[((size_t)(bt * NTOK + r0 + 8)) * CDIM + col] = o;
            }
        }
    }
}

// ---------------------------------------------------------------------------
// kernel_launch
// ---------------------------------------------------------------------------
extern "C" void kernel_launch(void* const* d_in, const int* in_sizes, int n_in,
                              void* d_out, int out_size)
{
    const float* x      = (const float*)d_in[0];
    const float* memory = (const float*)d_in[1];
    const float* w_q    = (const float*)d_in[2];
    const float* b_q    = (const float*)d_in[3];
    const float* w_kv   = (const float*)d_in[4];
    const float* b_kv   = (const float*)d_in[5];
    const float* w_proj = (const float*)d_in[6];
    const float* b_proj = (const float*)d_in[7];
    const float* rpb    = (const float*)d_in[8];
    float* out = (float*)d_out;

    float *gq, *gkv, *gao;
    cudaGetSymbolAddress((void**)&gq,  g_q);
    cudaGetSymbolAddress((void**)&gkv, g_kv);
    cudaGetSymbolAddress((void**)&gao, g_ao);

    const int SMEM = (2 * ASZ + 2 * BSZ) * 4;
    cudaFuncSetAttribute(gemm_mma<192>, cudaFuncAttributeMaxDynamicSharedMemorySize, SMEM);
    cudaFuncSetAttribute(gemm_mma<384>, cudaFuncAttributeMaxDynamicSharedMemorySize, SMEM);
    cudaFuncSetAttribute(attn_mma, cudaFuncAttributeMaxDynamicSharedMemorySize, ATTN_SMEM);

    // Q projection
    gemm_mma<192><<<dim3(M_Q / 128, 1), 256, SMEM>>>(x, w_q, b_q, gq);
    // KV projection
    gemm_mma<384><<<dim3(M_KV / 128, 2), 256, SMEM>>>(memory, w_kv, b_kv, gkv);
    // Tensor-core attention: 2 heads/CTA, 3 head-pairs, one CTA column per (b,t)
    attn_mma<<<dim3(BATCH * TT, NHEAD / HPC), HPC * 32, ATTN_SMEM>>>(gq, gkv, rpb, gao);
    // Output projection
    gemm_mma<192><<<dim3(M_KV / 128, 1), 256, SMEM>>>(gao, w_proj, b_proj, out);
}